// round 13
// baseline (speedup 1.0000x reference)
#include <cuda_runtime.h>
#include <math.h>

#define TOTN 128000
#define FIN 32
#define HD 64
#define HEADS 4
#define NL 4
#define NE 512000
#define NB 128
#define OBSD 1500
#define HSD 512
#define NOUTD 15
#define AD 15
#define VHD 128
#define SCAN_BLKS 125

typedef unsigned long long ull;

// ---------------- f32x2 helpers ----------------
__device__ __forceinline__ ull pk2(float x, float y) {
    ull r;
    asm("mov.b64 %0, {%1, %2};" : "=l"(r) : "f"(x), "f"(y));
    return r;
}
__device__ __forceinline__ float2 upk2(ull v) {
    float2 r;
    asm("mov.b64 {%0, %1}, %2;" : "=f"(r.x), "=f"(r.y) : "l"(v));
    return r;
}
__device__ __forceinline__ void fma2(ull& d, ull a, ull b) {
    asm("fma.rn.f32x2 %0, %1, %2, %0;" : "+l"(d) : "l"(a), "l"(b));
}

// ---------------- scratch ----------------
__device__ float g_x[TOTN * HD];
__device__ float g_qA[TOTN * HD];
__device__ float g_kA[TOTN * HD];
__device__ float g_vA[TOTN * HD];
__device__ float g_qB[TOTN * HD];
__device__ float g_kB[TOTN * HD];
__device__ float g_vB[TOTN * HD];
__device__ int   g_deg[TOTN];
__device__ int   g_start[TOTN + 1];
__device__ int   g_bsum[SCAN_BLKS];
__device__ int   g_csr[NE];
__device__ float g_gat[NB * AD];
__device__ float g_feat[NB * HSD];
__device__ float g_feat2[NB * HSD];
__device__ float g_vh[NB * VHD];
__device__ float g_vh2[NB * VHD];
__device__ float g_pacc[NB * HSD];

// ================= CSR build =================
__global__ void hist_kernel(const int* __restrict__ edst) {
    int e = blockIdx.x * 256 + threadIdx.x;
    if (e < NE) atomicAdd(&g_deg[edst[e]], 1);
}
__global__ void scan1_kernel() {
    __shared__ int ts[256];
    int tid = threadIdx.x;
    int base = blockIdx.x * 1024 + tid * 4;
    int a0 = g_deg[base], a1 = g_deg[base + 1], a2 = g_deg[base + 2], a3 = g_deg[base + 3];
    int s = a0 + a1 + a2 + a3;
    ts[tid] = s;
    __syncthreads();
#pragma unroll
    for (int off = 1; off < 256; off <<= 1) {
        int v = (tid >= off) ? ts[tid - off] : 0;
        __syncthreads();
        ts[tid] += v;
        __syncthreads();
    }
    int excl = ts[tid] - s;
    g_start[base] = excl;
    g_start[base + 1] = excl + a0;
    g_start[base + 2] = excl + a0 + a1;
    g_start[base + 3] = excl + a0 + a1 + a2;
    if (tid == 255) g_bsum[blockIdx.x] = ts[255];
}
__global__ void scan2_kernel() {
    __shared__ int ts[128];
    int tid = threadIdx.x;
    int v = (tid < SCAN_BLKS) ? g_bsum[tid] : 0;
    ts[tid] = v;
    __syncthreads();
#pragma unroll
    for (int off = 1; off < 128; off <<= 1) {
        int u = (tid >= off) ? ts[tid - off] : 0;
        __syncthreads();
        ts[tid] += u;
        __syncthreads();
    }
    if (tid < SCAN_BLKS) g_bsum[tid] = ts[tid] - v;
}
__global__ void scan3_kernel() {
    int i = blockIdx.x * 256 + threadIdx.x;
    if (i < TOTN) {
        g_start[i] += g_bsum[i >> 10];
        g_deg[i] = 0;
    }
    if (i == 0) g_start[TOTN] = NE;
}
__global__ void scatter_kernel(const int* __restrict__ esrc, const int* __restrict__ edst) {
    int e = blockIdx.x * 256 + threadIdx.x;
    if (e >= NE) return;
    int d = edst[e];
    int pos = atomicAdd(&g_deg[d], 1);
    g_csr[g_start[d] + pos] = esrc[e];
}

// ================= dup-B 64x64 GEMM core =================
// loader: 4096 elems of W -> ws[k*132 + 2c] duplicated pairs
__device__ __forceinline__ void load_w_dup(float* ws, const float* __restrict__ W, int tid) {
#pragma unroll
    for (int i = 0; i < 16; i++) {
        int idx = tid + i * 256;
        int k = idx >> 6, c = idx & 63;
        float w = W[idx];
        *(float2*)&ws[k * 132 + 2 * c] = make_float2(w, w);
    }
}

// ================= shared QKV tail: x(smem, transposed) @ {Wq,Wk,Wv} =================
__device__ __forceinline__ void qkv_tail(float* xs, float* ws, int tid, int n0,
                                         const float* __restrict__ Wq,
                                         const float* __restrict__ Wk,
                                         const float* __restrict__ Wv,
                                         float* __restrict__ qo, float* __restrict__ ko,
                                         float* __restrict__ vo) {
    int ty = tid >> 4, tx = tid & 15;
#pragma unroll
    for (int m = 0; m < 3; m++) {
        const float* W = (m == 0) ? Wq : (m == 1) ? Wk : Wv;
        float* O = (m == 0) ? qo : (m == 1) ? ko : vo;
        __syncthreads();
        load_w_dup(ws, W, tid);
        __syncthreads();
        ull acc[2][4] = {};
#pragma unroll
        for (int k = 0; k < 64; k++) {
            ull a0 = *(const ull*)&xs[k * 68 + ty * 4];
            ull a1 = *(const ull*)&xs[k * 68 + ty * 4 + 2];
            ulonglong2 bA = *(const ulonglong2*)&ws[k * 132 + tx * 8];
            ulonglong2 bB = *(const ulonglong2*)&ws[k * 132 + tx * 8 + 4];
            fma2(acc[0][0], a0, bA.x); fma2(acc[1][0], a1, bA.x);
            fma2(acc[0][1], a0, bA.y); fma2(acc[1][1], a1, bA.y);
            fma2(acc[0][2], a0, bB.x); fma2(acc[1][2], a1, bB.x);
            fma2(acc[0][3], a0, bB.y); fma2(acc[1][3], a1, bB.y);
        }
#pragma unroll
        for (int i2 = 0; i2 < 2; i2++) {
            float2 p0 = upk2(acc[i2][0]), p1 = upk2(acc[i2][1]);
            float2 p2 = upk2(acc[i2][2]), p3 = upk2(acc[i2][3]);
            int r0 = n0 + ty * 4 + i2 * 2;
            *(float4*)&O[r0 * HD + tx * 4] = make_float4(p0.x, p1.x, p2.x, p3.x);
            *(float4*)&O[(r0 + 1) * HD + tx * 4] = make_float4(p0.y, p1.y, p2.y, p3.y);
        }
    }
}

// ================= pre: inproj + QKV(layer0), 64-node tile =================
__global__ __launch_bounds__(256) void pre_kernel(const float* __restrict__ nf,
                                                  const float* __restrict__ Win,
                                                  const float* __restrict__ Wq,
                                                  const float* __restrict__ Wk,
                                                  const float* __restrict__ Wv,
                                                  float* __restrict__ qo, float* __restrict__ ko,
                                                  float* __restrict__ vo) {
    __shared__ float nfs[32 * 68];
    __shared__ float xs[64 * 68];
    __shared__ float sw[8448];
    int tid = threadIdx.x;
    int n0 = blockIdx.x * 64;
#pragma unroll
    for (int i = 0; i < 8; i++) {
        int idx = tid + i * 256;
        int r = idx >> 5, c = idx & 31;
        nfs[c * 68 + r] = nf[(n0 + r) * FIN + c];
    }
#pragma unroll
    for (int i = 0; i < 8; i++) { int idx = tid + i * 256; sw[idx] = Win[idx]; }
    __syncthreads();
    int ty = tid >> 4, tx = tid & 15;
    ull acc[2][4] = {};
#pragma unroll
    for (int k = 0; k < 32; k++) {
        ull a0 = *(const ull*)&nfs[k * 68 + ty * 4];
        ull a1 = *(const ull*)&nfs[k * 68 + ty * 4 + 2];
        float4 bv = *(const float4*)&sw[k * 64 + tx * 4];
        ull b2[4] = {pk2(bv.x, bv.x), pk2(bv.y, bv.y), pk2(bv.z, bv.z), pk2(bv.w, bv.w)};
#pragma unroll
        for (int j = 0; j < 4; j++) { fma2(acc[0][j], a0, b2[j]); fma2(acc[1][j], a1, b2[j]); }
    }
#pragma unroll
    for (int i2 = 0; i2 < 2; i2++) {
        float2 p0 = upk2(acc[i2][0]), p1 = upk2(acc[i2][1]);
        float2 p2 = upk2(acc[i2][2]), p3 = upk2(acc[i2][3]);
        int r0 = ty * 4 + i2 * 2;
        *(float4*)&g_x[(n0 + r0) * HD + tx * 4] = make_float4(p0.x, p1.x, p2.x, p3.x);
        *(float4*)&g_x[(n0 + r0 + 1) * HD + tx * 4] = make_float4(p0.y, p1.y, p2.y, p3.y);
        xs[(tx * 4 + 0) * 68 + r0] = p0.x; xs[(tx * 4 + 0) * 68 + r0 + 1] = p0.y;
        xs[(tx * 4 + 1) * 68 + r0] = p1.x; xs[(tx * 4 + 1) * 68 + r0 + 1] = p1.y;
        xs[(tx * 4 + 2) * 68 + r0] = p2.x; xs[(tx * 4 + 2) * 68 + r0 + 1] = p2.y;
        xs[(tx * 4 + 3) * 68 + r0] = p3.x; xs[(tx * 4 + 3) * 68 + r0 + 1] = p3.y;
    }
    qkv_tail(xs, sw, tid, n0, Wq, Wk, Wv, qo, ko, vo);
}

// ================= post: gather + O-proj + LN1 + FFN + LN2 + QKV(next) =================
// smem: xs 4352 | ws 8448 | hs 8704  = 21504 floats = 86016 B
#define POST_SMEM 86016
__global__ __launch_bounds__(256, 2) void post_kernel(
    const float* __restrict__ qin, const float* __restrict__ kin, const float* __restrict__ vin,
    const float* __restrict__ Wo, const float* __restrict__ g1v, const float* __restrict__ be1,
    const float* __restrict__ W1, const float* __restrict__ b1v,
    const float* __restrict__ W2, const float* __restrict__ b2v,
    const float* __restrict__ g2v, const float* __restrict__ be2,
    const float* __restrict__ Wq, const float* __restrict__ Wk, const float* __restrict__ Wv,
    float* __restrict__ qo, float* __restrict__ ko, float* __restrict__ vo) {
    extern __shared__ float smem[];
    float* xs = smem;            // [64][68]  4352 floats
    float* ws = smem + 4352;     // 8448 floats (dup'd weights / W1 natural / C tile)
    float* hs = ws + 8448;       // 8704 floats
    int tid = threadIdx.x;
    int n0 = blockIdx.x * 64;
    int ty = tid >> 4, tx = tid & 15;
    // stage Wo (dup'd) early: overlaps the latency-bound gather below
    load_w_dup(ws, Wo, tid);
    // ---- gather (thread per node,head) -> xs transposed ----
    {
        int r = tid >> 2, h = tid & 3;
        int node = n0 + r;
        const float4* q4 = (const float4*)&qin[node * HD + h * 16];
        float4 q0 = q4[0], q1 = q4[1], q2 = q4[2], q3 = q4[3];
        int s0 = g_start[node], s1 = g_start[node + 1];
        float denom = 0.f;
        float acc[16] = {};
        for (int i = s0; i < s1; i++) {
            int src = g_csr[i];
            const float4* k4 = (const float4*)&kin[src * HD + h * 16];
            float4 k0 = k4[0], k1 = k4[1], k2 = k4[2], k3 = k4[3];
            float p = q0.x * k0.x + q0.y * k0.y + q0.z * k0.z + q0.w * k0.w
                    + q1.x * k1.x + q1.y * k1.y + q1.z * k1.z + q1.w * k1.w
                    + q2.x * k2.x + q2.y * k2.y + q2.z * k2.z + q2.w * k2.w
                    + q3.x * k3.x + q3.y * k3.y + q3.z * k3.z + q3.w * k3.w;
            float w = __expf(p * 0.25f);
            const float4* v4 = (const float4*)&vin[src * HD + h * 16];
            float4 v0 = v4[0], v1 = v4[1], v2 = v4[2], v3 = v4[3];
            denom += w;
            acc[0] += w * v0.x;  acc[1] += w * v0.y;  acc[2] += w * v0.z;  acc[3] += w * v0.w;
            acc[4] += w * v1.x;  acc[5] += w * v1.y;  acc[6] += w * v1.z;  acc[7] += w * v1.w;
            acc[8] += w * v2.x;  acc[9] += w * v2.y;  acc[10] += w * v2.z; acc[11] += w * v2.w;
            acc[12] += w * v3.x; acc[13] += w * v3.y; acc[14] += w * v3.z; acc[15] += w * v3.w;
        }
        float inv = (denom > 0.f) ? 1.f / denom : 0.f;
#pragma unroll
        for (int j = 0; j < 16; j++) xs[(h * 16 + j) * 68 + r] = acc[j] * inv;
    }
    __syncthreads();
    // ---- O-proj GEMM (dup'd B) -> hs (stride 68) ----
    {
        ull acc[2][4] = {};
#pragma unroll
        for (int k = 0; k < 64; k++) {
            ull a0 = *(const ull*)&xs[k * 68 + ty * 4];
            ull a1 = *(const ull*)&xs[k * 68 + ty * 4 + 2];
            ulonglong2 bA = *(const ulonglong2*)&ws[k * 132 + tx * 8];
            ulonglong2 bB = *(const ulonglong2*)&ws[k * 132 + tx * 8 + 4];
            fma2(acc[0][0], a0, bA.x); fma2(acc[1][0], a1, bA.x);
            fma2(acc[0][1], a0, bA.y); fma2(acc[1][1], a1, bA.y);
            fma2(acc[0][2], a0, bB.x); fma2(acc[1][2], a1, bB.x);
            fma2(acc[0][3], a0, bB.y); fma2(acc[1][3], a1, bB.y);
        }
#pragma unroll
        for (int i2 = 0; i2 < 2; i2++) {
            float2 p0 = upk2(acc[i2][0]), p1 = upk2(acc[i2][1]);
            float2 p2 = upk2(acc[i2][2]), p3 = upk2(acc[i2][3]);
            int r0 = ty * 4 + i2 * 2;
            hs[r0 * 68 + tx * 4] = p0.x;     hs[r0 * 68 + tx * 4 + 1] = p1.x;
            hs[r0 * 68 + tx * 4 + 2] = p2.x; hs[r0 * 68 + tx * 4 + 3] = p3.x;
            hs[(r0 + 1) * 68 + tx * 4] = p0.y;     hs[(r0 + 1) * 68 + tx * 4 + 1] = p1.y;
            hs[(r0 + 1) * 68 + tx * 4 + 2] = p2.y; hs[(r0 + 1) * 68 + tx * 4 + 3] = p3.y;
        }
    }
    __syncthreads();
    // ---- LN1 (residual from g_x) -> xs transposed ----
    {
        int r = tid >> 2, p = tid & 3;
        float vals[16];
        float sum = 0.f;
#pragma unroll
        for (int j = 0; j < 16; j++) {
            int c = p * 16 + j;
            float t = hs[r * 68 + c] + g_x[(n0 + r) * HD + c];
            vals[j] = t; sum += t;
        }
        sum += __shfl_xor_sync(0xffffffffu, sum, 1);
        sum += __shfl_xor_sync(0xffffffffu, sum, 2);
        float mean = sum * (1.f / 64.f);
        float vsum = 0.f;
#pragma unroll
        for (int j = 0; j < 16; j++) { float d = vals[j] - mean; vsum += d * d; }
        vsum += __shfl_xor_sync(0xffffffffu, vsum, 1);
        vsum += __shfl_xor_sync(0xffffffffu, vsum, 2);
        float rstd = rsqrtf(vsum * (1.f / 64.f) + 1e-5f);
#pragma unroll
        for (int j = 0; j < 16; j++) {
            int c = p * 16 + j;
            xs[c * 68 + r] = (vals[j] - mean) * rstd * g1v[c] + be1[c];
        }
    }
    __syncthreads();
    // ---- FFN GEMM1 (64->128) + ReLU -> hs transposed (W1 natural, a-dup) ----
#pragma unroll
    for (int i = 0; i < 32; i++) {
        int idx = tid + i * 256;
        ws[(idx >> 7) * 132 + (idx & 127)] = W1[idx];
    }
    __syncthreads();
    {
        ull acc1[4][4] = {};
#pragma unroll
        for (int k = 0; k < 64; k++) {
            float4 av = *(const float4*)&xs[k * 68 + ty * 4];
            ull a2[4] = {pk2(av.x, av.x), pk2(av.y, av.y), pk2(av.z, av.z), pk2(av.w, av.w)};
            ull b2[4];
#pragma unroll
            for (int j2 = 0; j2 < 4; j2++) b2[j2] = *(const ull*)&ws[k * 132 + tx * 8 + j2 * 2];
#pragma unroll
            for (int i = 0; i < 4; i++)
#pragma unroll
                for (int j2 = 0; j2 < 4; j2++) fma2(acc1[i][j2], a2[i], b2[j2]);
        }
#pragma unroll
        for (int i = 0; i < 4; i++)
#pragma unroll
            for (int j2 = 0; j2 < 4; j2++) {
                float2 pv = upk2(acc1[i][j2]);
                int c0 = tx * 8 + j2 * 2;
                hs[c0 * 68 + ty * 4 + i] = fmaxf(pv.x + b1v[c0], 0.f);
                hs[(c0 + 1) * 68 + ty * 4 + i] = fmaxf(pv.y + b1v[c0 + 1], 0.f);
            }
    }
    // ---- FFN GEMM2 (128->64), W2 dup'd in two 64-k halves ----
    ull acc2[2][4] = {};
#pragma unroll
    for (int half = 0; half < 2; half++) {
        __syncthreads();
#pragma unroll
        for (int i = 0; i < 16; i++) {
            int idx = tid + i * 256;
            int k = idx >> 6, c = idx & 63;
            float w = W2[(half * 64 + k) * HD + c];
            *(float2*)&ws[k * 132 + 2 * c] = make_float2(w, w);
        }
        __syncthreads();
#pragma unroll
        for (int kk = 0; kk < 64; kk++) {
            int k = half * 64 + kk;
            ull a0 = *(const ull*)&hs[k * 68 + ty * 4];
            ull a1 = *(const ull*)&hs[k * 68 + ty * 4 + 2];
            ulonglong2 bA = *(const ulonglong2*)&ws[kk * 132 + tx * 8];
            ulonglong2 bB = *(const ulonglong2*)&ws[kk * 132 + tx * 8 + 4];
            fma2(acc2[0][0], a0, bA.x); fma2(acc2[1][0], a1, bA.x);
            fma2(acc2[0][1], a0, bA.y); fma2(acc2[1][1], a1, bA.y);
            fma2(acc2[0][2], a0, bB.x); fma2(acc2[1][2], a1, bB.x);
            fma2(acc2[0][3], a0, bB.y); fma2(acc2[1][3], a1, bB.y);
        }
    }
    __syncthreads();   // W2 reads done; reuse ws for C
#pragma unroll
    for (int i2 = 0; i2 < 2; i2++) {
        float2 p0 = upk2(acc2[i2][0]), p1 = upk2(acc2[i2][1]);
        float2 p2 = upk2(acc2[i2][2]), p3 = upk2(acc2[i2][3]);
        int r0 = ty * 4 + i2 * 2;
        ws[r0 * 68 + tx * 4] = p0.x + b2v[tx * 4];
        ws[r0 * 68 + tx * 4 + 1] = p1.x + b2v[tx * 4 + 1];
        ws[r0 * 68 + tx * 4 + 2] = p2.x + b2v[tx * 4 + 2];
        ws[r0 * 68 + tx * 4 + 3] = p3.x + b2v[tx * 4 + 3];
        ws[(r0 + 1) * 68 + tx * 4] = p0.y + b2v[tx * 4];
        ws[(r0 + 1) * 68 + tx * 4 + 1] = p1.y + b2v[tx * 4 + 1];
        ws[(r0 + 1) * 68 + tx * 4 + 2] = p2.y + b2v[tx * 4 + 2];
        ws[(r0 + 1) * 68 + tx * 4 + 3] = p3.y + b2v[tx * 4 + 3];
    }
    __syncthreads();
    // ---- LN2 (residual from xs = LN1 out) -> g_x, regs ----
    int r2 = tid >> 2, p2 = tid & 3;
    float outs[16];
    {
        float vals[16];
        float sum = 0.f;
#pragma unroll
        for (int j = 0; j < 16; j++) {
            int c = p2 * 16 + j;
            float t = ws[r2 * 68 + c] + xs[c * 68 + r2];
            vals[j] = t; sum += t;
        }
        sum += __shfl_xor_sync(0xffffffffu, sum, 1);
        sum += __shfl_xor_sync(0xffffffffu, sum, 2);
        float mean = sum * (1.f / 64.f);
        float vsum = 0.f;
#pragma unroll
        for (int j = 0; j < 16; j++) { float d = vals[j] - mean; vsum += d * d; }
        vsum += __shfl_xor_sync(0xffffffffu, vsum, 1);
        vsum += __shfl_xor_sync(0xffffffffu, vsum, 2);
        float rstd = rsqrtf(vsum * (1.f / 64.f) + 1e-5f);
#pragma unroll
        for (int j = 0; j < 16; j++) {
            int c = p2 * 16 + j;
            outs[j] = (vals[j] - mean) * rstd * g2v[c] + be2[c];
            g_x[(n0 + r2) * HD + c] = outs[j];
        }
    }
    // ---- QKV for next layer ----
    if (Wq) {
        __syncthreads();   // residual reads of xs done
#pragma unroll
        for (int j = 0; j < 16; j++) xs[(p2 * 16 + j) * 68 + r2] = outs[j];
        qkv_tail(xs, ws, tid, n0, Wq, Wk, Wv, qo, ko, vo);
    }
}

// ================= readout =================
__global__ void readout_kernel(const int* __restrict__ agent, const float* __restrict__ Wr,
                               const float* __restrict__ br) {
    int t = blockIdx.x * blockDim.x + threadIdx.x;
    if (t >= NB * AD) return;
    int b = t / AD, a = t % AD;
    int node = agent[b];
    float s = br[a];
    const float* xr = g_x + node * HD;
#pragma unroll
    for (int h = 0; h < HD; h++) s += xr[h] * Wr[h * AD + a];
    g_gat[t] = s;
}

// ================= small GEMM helpers (M=128) =================
__global__ void init_bias_kernel(float* dst, const float* __restrict__ bias, int rows, int cols) {
    int idx = blockIdx.x * blockDim.x + threadIdx.x;
    if (idx < rows * cols) dst[idx] = bias[idx % cols];
}
__global__ void tanh_kernel(float* dst, const float* __restrict__ src, int n) {
    int idx = blockIdx.x * blockDim.x + threadIdx.x;
    if (idx < n) dst[idx] = tanhf(src[idx]);
}
__global__ void gemm_partial_kernel(const float* __restrict__ Apre, int preLen, int preLd,
                                    const float* __restrict__ Amain, int mainLd,
                                    const float* __restrict__ W, int ldw, int Ktot,
                                    float* Cacc, int ldc) {
    __shared__ float As[32 * 132];
    __shared__ float Ws[32 * 68];
    int colBase = blockIdx.x * 64;
    int kchunks = (Ktot + 31) / 32;
    int per = (kchunks + gridDim.y - 1) / gridDim.y;
    int c0 = blockIdx.y * per;
    int c1 = min(c0 + per, kchunks);
    int tid = threadIdx.x;
    int ty = tid >> 4, tx = tid & 15;
    ull acc[4][4] = {};
    for (int c = c0; c < c1; c++) {
        int kb = c * 32;
        __syncthreads();
#pragma unroll
        for (int i = 0; i < 16; i++) {
            int idx = tid + i * 256;
            int r = idx >> 5, kk = idx & 31;
            int k = kb + kk;
            float vv = 0.f;
            if (k < Ktot)
                vv = (k < preLen) ? Apre[r * preLd + k] : Amain[r * mainLd + k - preLen];
            As[kk * 132 + r] = vv;
        }
#pragma unroll
        for (int i = 0; i < 8; i++) {
            int idx = tid + i * 256;
            int kk = idx >> 6, j = idx & 63;
            int k = kb + kk;
            Ws[kk * 68 + j] = (k < Ktot) ? W[k * ldw + colBase + j] : 0.f;
        }
        __syncthreads();
#pragma unroll
        for (int kk = 0; kk < 32; kk++) {
            ull a2[4];
#pragma unroll
            for (int i2 = 0; i2 < 4; i2++)
                a2[i2] = *(const ull*)&As[kk * 132 + ty * 8 + i2 * 2];
            float4 bv = *(const float4*)&Ws[kk * 68 + tx * 4];
            ull b2[4] = {pk2(bv.x, bv.x), pk2(bv.y, bv.y), pk2(bv.z, bv.z), pk2(bv.w, bv.w)};
#pragma unroll
            for (int i2 = 0; i2 < 4; i2++)
#pragma unroll
                for (int j = 0; j < 4; j++) fma2(acc[i2][j], a2[i2], b2[j]);
        }
    }
#pragma unroll
    for (int i2 = 0; i2 < 4; i2++)
#pragma unroll
        for (int j = 0; j < 4; j++) {
            float2 pv = upk2(acc[i2][j]);
            atomicAdd(&Cacc[(ty * 8 + i2 * 2) * ldc + colBase + tx * 4 + j], pv.x);
            atomicAdd(&Cacc[(ty * 8 + i2 * 2 + 1) * ldc + colBase + tx * 4 + j], pv.y);
        }
}

// ================= heads =================
__global__ void logits_kernel(const float* __restrict__ Wlog, const float* __restrict__ blog,
                              float* out) {
    int t = blockIdx.x * blockDim.x + threadIdx.x;
    if (t >= NB * NOUTD) return;
    int b = t / NOUTD, o = t % NOUTD;
    float s = blog[o];
    const float* fr = g_feat2 + b * HSD;
    for (int k = 0; k < HSD; k++) s += fr[k] * Wlog[k * NOUTD + o];
    out[t] = s;
}
__global__ void value_kernel(const float* __restrict__ Wvo, const float* __restrict__ bvo,
                             float* out) {
    int b = blockIdx.x * blockDim.x + threadIdx.x;
    if (b >= NB) return;
    float s = bvo[0];
    const float* vr = g_vh2 + b * VHD;
#pragma unroll
    for (int k = 0; k < VHD; k++) s += vr[k] * Wvo[k];
    out[NB * NOUTD + b] = s;
}

// ================= launch =================
extern "C" void kernel_launch(void* const* d_in, const int* in_sizes, int n_in,
                              void* d_out, int out_size) {
    const float* nf     = (const float*)d_in[0];
    const float* obs    = (const float*)d_in[1];
    const int*   esrc   = (const int*)d_in[2];
    const int*   edst   = (const int*)d_in[3];
    const int*   agent  = (const int*)d_in[4];
    const float* Win    = (const float*)d_in[5];
    const float* Wq     = (const float*)d_in[6];
    const float* Wk     = (const float*)d_in[7];
    const float* Wv     = (const float*)d_in[8];
    const float* Wo     = (const float*)d_in[9];
    const float* ln1g   = (const float*)d_in[10];
    const float* ln1b   = (const float*)d_in[11];
    const float* W1     = (const float*)d_in[12];
    const float* b1     = (const float*)d_in[13];
    const float* W2     = (const float*)d_in[14];
    const float* b2     = (const float*)d_in[15];
    const float* ln2g   = (const float*)d_in[16];
    const float* ln2b   = (const float*)d_in[17];
    const float* Wr     = (const float*)d_in[18];
    const float* br     = (const float*)d_in[19];
    const float* Wp1    = (const float*)d_in[20];
    const float* bp1    = (const float*)d_in[21];
    const float* Wp2    = (const float*)d_in[22];
    const float* bp2    = (const float*)d_in[23];
    const float* Wlog   = (const float*)d_in[24];
    const float* blog   = (const float*)d_in[25];
    const float* Wv1    = (const float*)d_in[26];
    const float* bv1    = (const float*)d_in[27];
    const float* Wv2    = (const float*)d_in[28];
    const float* bv2    = (const float*)d_in[29];
    const float* Wvo    = (const float*)d_in[30];
    const float* bvo    = (const float*)d_in[31];
    float* out = (float*)d_out;

    cudaFuncSetAttribute(post_kernel, cudaFuncAttributeMaxDynamicSharedMemorySize, POST_SMEM);

    float *p_gat, *p_feat, *p_feat2, *p_vh, *p_vh2, *p_pacc;
    float *qA, *kA, *vA, *qB, *kB, *vB;
    int* p_deg;
    cudaGetSymbolAddress((void**)&p_gat, g_gat);
    cudaGetSymbolAddress((void**)&p_feat, g_feat);
    cudaGetSymbolAddress((void**)&p_feat2, g_feat2);
    cudaGetSymbolAddress((void**)&p_vh, g_vh);
    cudaGetSymbolAddress((void**)&p_vh2, g_vh2);
    cudaGetSymbolAddress((void**)&p_pacc, g_pacc);
    cudaGetSymbolAddress((void**)&qA, g_qA);
    cudaGetSymbolAddress((void**)&kA, g_kA);
    cudaGetSymbolAddress((void**)&vA, g_vA);
    cudaGetSymbolAddress((void**)&qB, g_qB);
    cudaGetSymbolAddress((void**)&kB, g_kB);
    cudaGetSymbolAddress((void**)&vB, g_vB);
    cudaGetSymbolAddress((void**)&p_deg, g_deg);

    // CSR build
    cudaMemsetAsync(p_deg, 0, TOTN * sizeof(int));
    hist_kernel<<<(NE + 255) / 256, 256>>>(edst);
    scan1_kernel<<<SCAN_BLKS, 256>>>();
    scan2_kernel<<<1, 128>>>();
    scan3_kernel<<<(TOTN + 255) / 256, 256>>>();
    scatter_kernel<<<(NE + 255) / 256, 256>>>(esrc, edst);

    // inproj + QKV layer0
    pre_kernel<<<TOTN / 64, 256>>>(nf, Win, Wq, Wk, Wv, qA, kA, vA);

    for (int l = 0; l < NL; l++) {
        const float* qi = (l & 1) ? qB : qA;
        const float* ki = (l & 1) ? kB : kA;
        const float* vi = (l & 1) ? vB : vA;
        float* qo = (l & 1) ? qA : qB;
        float* ko = (l & 1) ? kA : kB;
        float* vo = (l & 1) ? vA : vB;
        bool last = (l == NL - 1);
        post_kernel<<<TOTN / 64, 256, POST_SMEM>>>(
            qi, ki, vi,
            Wo + l * HD * HD, ln1g + l * HD, ln1b + l * HD,
            W1 + l * HD * 2 * HD, b1 + l * 2 * HD,
            W2 + l * 2 * HD * HD, b2 + l * HD,
            ln2g + l * HD, ln2b + l * HD,
            last ? nullptr : Wq + (l + 1) * HD * HD,
            last ? nullptr : Wk + (l + 1) * HD * HD,
            last ? nullptr : Wv + (l + 1) * HD * HD,
            qo, ko, vo);
    }

    readout_kernel<<<(NB * AD + 255) / 256, 256>>>(agent, Wr, br);

    // policy head
    init_bias_kernel<<<(NB * HSD + 255) / 256, 256>>>(p_pacc, bp1, NB, HSD);
    gemm_partial_kernel<<<dim3(8, 8), 256>>>(p_gat, AD, AD, obs, OBSD, Wp1, HSD, AD + OBSD,
                                             p_pacc, HSD);
    tanh_kernel<<<(NB * HSD + 255) / 256, 256>>>(p_feat, p_pacc, NB * HSD);

    init_bias_kernel<<<(NB * HSD + 255) / 256, 256>>>(p_pacc, bp2, NB, HSD);
    gemm_partial_kernel<<<dim3(8, 4), 256>>>(nullptr, 0, 0, p_feat, HSD, Wp2, HSD, HSD,
                                             p_pacc, HSD);
    tanh_kernel<<<(NB * HSD + 255) / 256, 256>>>(p_feat2, p_pacc, NB * HSD);

    logits_kernel<<<(NB * NOUTD + 255) / 256, 256>>>(Wlog, blog, out);

    // value head
    init_bias_kernel<<<(NB * VHD + 255) / 256, 256>>>(p_pacc, bv1, NB, VHD);
    gemm_partial_kernel<<<dim3(2, 8), 256>>>(nullptr, 0, 0, obs, OBSD, Wv1, VHD, OBSD,
                                             p_pacc, VHD);
    tanh_kernel<<<(NB * VHD + 255) / 256, 256>>>(p_vh, p_pacc, NB * VHD);

    init_bias_kernel<<<(NB * VHD + 255) / 256, 256>>>(p_pacc, bv2, NB, VHD);
    gemm_partial_kernel<<<dim3(2, 1), 256>>>(nullptr, 0, 0, p_vh, VHD, Wv2, VHD, VHD,
                                             p_pacc, VHD);
    tanh_kernel<<<(NB * VHD + 255) / 256, 256>>>(p_vh2, p_pacc, NB * VHD);

    value_kernel<<<1, NB>>>(Wvo, bvo, out);
}

// round 16
// speedup vs baseline: 1.6277x; 1.6277x over previous
#include <cuda_runtime.h>
#include <math.h>

#define TOTN 128000
#define FIN 32
#define HD 64
#define HEADS 4
#define NL 4
#define NE 512000
#define NB 128
#define OBSD 1500
#define HSD 512
#define NOUTD 15
#define AD 15
#define VHD 128
#define SCAN_BLKS 125

typedef unsigned long long ull;

// ---------------- f32x2 helpers ----------------
__device__ __forceinline__ ull pk2(float x, float y) {
    ull r;
    asm("mov.b64 %0, {%1, %2};" : "=l"(r) : "f"(x), "f"(y));
    return r;
}
__device__ __forceinline__ float2 upk2(ull v) {
    float2 r;
    asm("mov.b64 {%0, %1}, %2;" : "=f"(r.x), "=f"(r.y) : "l"(v));
    return r;
}
__device__ __forceinline__ void fma2(ull& d, ull a, ull b) {
    asm("fma.rn.f32x2 %0, %1, %2, %0;" : "+l"(d) : "l"(a), "l"(b));
}

// ---------------- scratch ----------------
__device__ float g_x[TOTN * HD];
__device__ float g_qA[TOTN * HD];
__device__ float g_kA[TOTN * HD];
__device__ float g_vA[TOTN * HD];
__device__ float g_qB[TOTN * HD];
__device__ float g_kB[TOTN * HD];
__device__ float g_vB[TOTN * HD];
__device__ int   g_deg[TOTN];
__device__ int   g_start[TOTN + 1];
__device__ int   g_bsum[SCAN_BLKS];
__device__ int   g_csr[NE];
__device__ float g_gat[NB * AD];
__device__ float g_feat[NB * HSD];
__device__ float g_feat2[NB * HSD];
__device__ float g_vh[NB * VHD];
__device__ float g_vh2[NB * VHD];
__device__ float g_pacc[NB * HSD];

// ================= CSR build =================
__global__ void hist_kernel(const int* __restrict__ edst) {
    int e = blockIdx.x * 256 + threadIdx.x;
    if (e < NE) atomicAdd(&g_deg[edst[e]], 1);
}
__global__ void scan1_kernel() {
    __shared__ int ts[256];
    int tid = threadIdx.x;
    int base = blockIdx.x * 1024 + tid * 4;
    int a0 = g_deg[base], a1 = g_deg[base + 1], a2 = g_deg[base + 2], a3 = g_deg[base + 3];
    int s = a0 + a1 + a2 + a3;
    ts[tid] = s;
    __syncthreads();
#pragma unroll
    for (int off = 1; off < 256; off <<= 1) {
        int v = (tid >= off) ? ts[tid - off] : 0;
        __syncthreads();
        ts[tid] += v;
        __syncthreads();
    }
    int excl = ts[tid] - s;
    g_start[base] = excl;
    g_start[base + 1] = excl + a0;
    g_start[base + 2] = excl + a0 + a1;
    g_start[base + 3] = excl + a0 + a1 + a2;
    if (tid == 255) g_bsum[blockIdx.x] = ts[255];
}
__global__ void scan2_kernel() {
    __shared__ int ts[128];
    int tid = threadIdx.x;
    int v = (tid < SCAN_BLKS) ? g_bsum[tid] : 0;
    ts[tid] = v;
    __syncthreads();
#pragma unroll
    for (int off = 1; off < 128; off <<= 1) {
        int u = (tid >= off) ? ts[tid - off] : 0;
        __syncthreads();
        ts[tid] += u;
        __syncthreads();
    }
    if (tid < SCAN_BLKS) g_bsum[tid] = ts[tid] - v;
}
__global__ void scan3_kernel() {
    int i = blockIdx.x * 256 + threadIdx.x;
    if (i < TOTN) {
        g_start[i] += g_bsum[i >> 10];
        g_deg[i] = 0;
    }
    if (i == 0) g_start[TOTN] = NE;
}
__global__ void scatter_kernel(const int* __restrict__ esrc, const int* __restrict__ edst) {
    int e = blockIdx.x * 256 + threadIdx.x;
    if (e >= NE) return;
    int d = edst[e];
    int pos = atomicAdd(&g_deg[d], 1);
    g_csr[g_start[d] + pos] = esrc[e];
}

// ================= shared QKV tail: x(smem, transposed) @ {Wq,Wk,Wv} =================
__device__ __forceinline__ void qkv_tail(float* xs, float* sw, int tid, int n0,
                                         const float* __restrict__ Wq,
                                         const float* __restrict__ Wk,
                                         const float* __restrict__ Wv,
                                         float* __restrict__ qo, float* __restrict__ ko,
                                         float* __restrict__ vo) {
    int ty = tid >> 4, tx = tid & 15;
#pragma unroll
    for (int m = 0; m < 3; m++) {
        const float* W = (m == 0) ? Wq : (m == 1) ? Wk : Wv;
        float* O = (m == 0) ? qo : (m == 1) ? ko : vo;
        __syncthreads();
#pragma unroll
        for (int i = 0; i < 16; i++) { int idx = tid + i * 256; sw[idx] = W[idx]; }
        __syncthreads();
        ull acc[2][4] = {};
#pragma unroll
        for (int k = 0; k < 64; k++) {
            ull a0 = *(const ull*)&xs[k * 68 + ty * 4];
            ull a1 = *(const ull*)&xs[k * 68 + ty * 4 + 2];
            float4 bv = *(const float4*)&sw[k * 64 + tx * 4];
            ull b2[4] = {pk2(bv.x, bv.x), pk2(bv.y, bv.y), pk2(bv.z, bv.z), pk2(bv.w, bv.w)};
#pragma unroll
            for (int j = 0; j < 4; j++) { fma2(acc[0][j], a0, b2[j]); fma2(acc[1][j], a1, b2[j]); }
        }
#pragma unroll
        for (int i2 = 0; i2 < 2; i2++) {
            float2 p0 = upk2(acc[i2][0]), p1 = upk2(acc[i2][1]);
            float2 p2 = upk2(acc[i2][2]), p3 = upk2(acc[i2][3]);
            int r0 = n0 + ty * 4 + i2 * 2;
            *(float4*)&O[r0 * HD + tx * 4] = make_float4(p0.x, p1.x, p2.x, p3.x);
            *(float4*)&O[(r0 + 1) * HD + tx * 4] = make_float4(p0.y, p1.y, p2.y, p3.y);
        }
    }
}

// ================= pre: inproj + QKV(layer0), 64-node tile =================
__global__ __launch_bounds__(256) void pre_kernel(const float* __restrict__ nf,
                                                  const float* __restrict__ Win,
                                                  const float* __restrict__ Wq,
                                                  const float* __restrict__ Wk,
                                                  const float* __restrict__ Wv,
                                                  float* __restrict__ qo, float* __restrict__ ko,
                                                  float* __restrict__ vo) {
    __shared__ float nfs[32 * 68];
    __shared__ float xs[64 * 68];
    __shared__ float sw[4096];
    int tid = threadIdx.x;
    int n0 = blockIdx.x * 64;
#pragma unroll
    for (int i = 0; i < 8; i++) {
        int idx = tid + i * 256;
        int r = idx >> 5, c = idx & 31;
        nfs[c * 68 + r] = nf[(n0 + r) * FIN + c];
    }
#pragma unroll
    for (int i = 0; i < 8; i++) { int idx = tid + i * 256; sw[idx] = Win[idx]; }
    __syncthreads();
    int ty = tid >> 4, tx = tid & 15;
    ull acc[2][4] = {};
#pragma unroll
    for (int k = 0; k < 32; k++) {
        ull a0 = *(const ull*)&nfs[k * 68 + ty * 4];
        ull a1 = *(const ull*)&nfs[k * 68 + ty * 4 + 2];
        float4 bv = *(const float4*)&sw[k * 64 + tx * 4];
        ull b2[4] = {pk2(bv.x, bv.x), pk2(bv.y, bv.y), pk2(bv.z, bv.z), pk2(bv.w, bv.w)};
#pragma unroll
        for (int j = 0; j < 4; j++) { fma2(acc[0][j], a0, b2[j]); fma2(acc[1][j], a1, b2[j]); }
    }
#pragma unroll
    for (int i2 = 0; i2 < 2; i2++) {
        float2 p0 = upk2(acc[i2][0]), p1 = upk2(acc[i2][1]);
        float2 p2 = upk2(acc[i2][2]), p3 = upk2(acc[i2][3]);
        int r0 = ty * 4 + i2 * 2;
        *(float4*)&g_x[(n0 + r0) * HD + tx * 4] = make_float4(p0.x, p1.x, p2.x, p3.x);
        *(float4*)&g_x[(n0 + r0 + 1) * HD + tx * 4] = make_float4(p0.y, p1.y, p2.y, p3.y);
        xs[(tx * 4 + 0) * 68 + r0] = p0.x; xs[(tx * 4 + 0) * 68 + r0 + 1] = p0.y;
        xs[(tx * 4 + 1) * 68 + r0] = p1.x; xs[(tx * 4 + 1) * 68 + r0 + 1] = p1.y;
        xs[(tx * 4 + 2) * 68 + r0] = p2.x; xs[(tx * 4 + 2) * 68 + r0 + 1] = p2.y;
        xs[(tx * 4 + 3) * 68 + r0] = p3.x; xs[(tx * 4 + 3) * 68 + r0 + 1] = p3.y;
    }
    qkv_tail(xs, sw, tid, n0, Wq, Wk, Wv, qo, ko, vo);
}

// ================= post: gather + O-proj + LN1 + FFN + LN2 + QKV(next) =================
#define POST_SMEM 87040
__global__ __launch_bounds__(256, 2) void post_kernel(
    const float* __restrict__ qin, const float* __restrict__ kin, const float* __restrict__ vin,
    const float* __restrict__ Wo, const float* __restrict__ g1v, const float* __restrict__ be1,
    const float* __restrict__ W1, const float* __restrict__ b1v,
    const float* __restrict__ W2, const float* __restrict__ b2v,
    const float* __restrict__ g2v, const float* __restrict__ be2,
    const float* __restrict__ Wq, const float* __restrict__ Wk, const float* __restrict__ Wv,
    float* __restrict__ qo, float* __restrict__ ko, float* __restrict__ vo) {
    extern __shared__ float smem[];
    float* xs = smem;            // [64][68]  4352 floats
    float* sw = smem + 4352;     // 8704 floats
    float* hs = sw + 8704;       // 8704 floats
    int tid = threadIdx.x;
    int n0 = blockIdx.x * 64;
    int ty = tid >> 4, tx = tid & 15;
    // stage Wo early: LDG/STS overlap the latency-bound gather below (no sync needed yet)
#pragma unroll
    for (int i = 0; i < 16; i++) { int idx = tid + i * 256; sw[idx] = Wo[idx]; }
    // ---- gather (thread per node,head) -> xs transposed ----
    // k AND v rows are loaded together BEFORE the q.k dot so all 8 loads of an
    // edge are in flight concurrently (v-wait hides under p/exp computation).
    {
        int r = tid >> 2, h = tid & 3;
        int node = n0 + r;
        const float4* q4 = (const float4*)&qin[node * HD + h * 16];
        float4 q0 = q4[0], q1 = q4[1], q2 = q4[2], q3 = q4[3];
        int s0 = g_start[node], s1 = g_start[node + 1];
        float denom = 0.f;
        float acc[16] = {};
        for (int i = s0; i < s1; i++) {
            int src = g_csr[i];
            const float4* k4 = (const float4*)&kin[src * HD + h * 16];
            const float4* v4 = (const float4*)&vin[src * HD + h * 16];
            float4 k0 = k4[0], k1 = k4[1], k2 = k4[2], k3 = k4[3];
            float4 v0 = v4[0], v1 = v4[1], v2 = v4[2], v3 = v4[3];
            float p = q0.x * k0.x + q0.y * k0.y + q0.z * k0.z + q0.w * k0.w
                    + q1.x * k1.x + q1.y * k1.y + q1.z * k1.z + q1.w * k1.w
                    + q2.x * k2.x + q2.y * k2.y + q2.z * k2.z + q2.w * k2.w
                    + q3.x * k3.x + q3.y * k3.y + q3.z * k3.z + q3.w * k3.w;
            float w = __expf(p * 0.25f);
            denom += w;
            acc[0] += w * v0.x;  acc[1] += w * v0.y;  acc[2] += w * v0.z;  acc[3] += w * v0.w;
            acc[4] += w * v1.x;  acc[5] += w * v1.y;  acc[6] += w * v1.z;  acc[7] += w * v1.w;
            acc[8] += w * v2.x;  acc[9] += w * v2.y;  acc[10] += w * v2.z; acc[11] += w * v2.w;
            acc[12] += w * v3.x; acc[13] += w * v3.y; acc[14] += w * v3.z; acc[15] += w * v3.w;
        }
        float inv = (denom > 0.f) ? 1.f / denom : 0.f;
#pragma unroll
        for (int j = 0; j < 16; j++) xs[(h * 16 + j) * 68 + r] = acc[j] * inv;
    }
    __syncthreads();
    // ---- O-proj GEMM -> hs (stride 68) ----
    {
        ull acc[2][4] = {};
#pragma unroll
        for (int k = 0; k < 64; k++) {
            ull a0 = *(const ull*)&xs[k * 68 + ty * 4];
            ull a1 = *(const ull*)&xs[k * 68 + ty * 4 + 2];
            float4 bv = *(const float4*)&sw[k * 64 + tx * 4];
            ull b2[4] = {pk2(bv.x, bv.x), pk2(bv.y, bv.y), pk2(bv.z, bv.z), pk2(bv.w, bv.w)};
#pragma unroll
            for (int j = 0; j < 4; j++) { fma2(acc[0][j], a0, b2[j]); fma2(acc[1][j], a1, b2[j]); }
        }
#pragma unroll
        for (int i2 = 0; i2 < 2; i2++) {
            float2 p0 = upk2(acc[i2][0]), p1 = upk2(acc[i2][1]);
            float2 p2 = upk2(acc[i2][2]), p3 = upk2(acc[i2][3]);
            int r0 = ty * 4 + i2 * 2;
            hs[r0 * 68 + tx * 4] = p0.x;     hs[r0 * 68 + tx * 4 + 1] = p1.x;
            hs[r0 * 68 + tx * 4 + 2] = p2.x; hs[r0 * 68 + tx * 4 + 3] = p3.x;
            hs[(r0 + 1) * 68 + tx * 4] = p0.y;     hs[(r0 + 1) * 68 + tx * 4 + 1] = p1.y;
            hs[(r0 + 1) * 68 + tx * 4 + 2] = p2.y; hs[(r0 + 1) * 68 + tx * 4 + 3] = p3.y;
        }
    }
    __syncthreads();
    // ---- LN1 (residual from g_x) -> xs transposed ----
    {
        int r = tid >> 2, p = tid & 3;
        float vals[16];
        float sum = 0.f;
#pragma unroll
        for (int j = 0; j < 16; j++) {
            int c = p * 16 + j;
            float t = hs[r * 68 + c] + g_x[(n0 + r) * HD + c];
            vals[j] = t; sum += t;
        }
        sum += __shfl_xor_sync(0xffffffffu, sum, 1);
        sum += __shfl_xor_sync(0xffffffffu, sum, 2);
        float mean = sum * (1.f / 64.f);
        float vsum = 0.f;
#pragma unroll
        for (int j = 0; j < 16; j++) { float d = vals[j] - mean; vsum += d * d; }
        vsum += __shfl_xor_sync(0xffffffffu, vsum, 1);
        vsum += __shfl_xor_sync(0xffffffffu, vsum, 2);
        float rstd = rsqrtf(vsum * (1.f / 64.f) + 1e-5f);
#pragma unroll
        for (int j = 0; j < 16; j++) {
            int c = p * 16 + j;
            xs[c * 68 + r] = (vals[j] - mean) * rstd * g1v[c] + be1[c];
        }
    }
    __syncthreads();
    // ---- FFN GEMM1 (64->128) + ReLU -> hs transposed ----
#pragma unroll
    for (int i = 0; i < 32; i++) {
        int idx = tid + i * 256;
        sw[(idx >> 7) * 132 + (idx & 127)] = W1[idx];
    }
    __syncthreads();
    {
        ull acc1[4][4] = {};
#pragma unroll
        for (int k = 0; k < 64; k++) {
            float4 av = *(const float4*)&xs[k * 68 + ty * 4];
            ull a2[4] = {pk2(av.x, av.x), pk2(av.y, av.y), pk2(av.z, av.z), pk2(av.w, av.w)};
            ull b2[4];
#pragma unroll
            for (int j2 = 0; j2 < 4; j2++) b2[j2] = *(const ull*)&sw[k * 132 + tx * 8 + j2 * 2];
#pragma unroll
            for (int i = 0; i < 4; i++)
#pragma unroll
                for (int j2 = 0; j2 < 4; j2++) fma2(acc1[i][j2], a2[i], b2[j2]);
        }
#pragma unroll
        for (int i = 0; i < 4; i++)
#pragma unroll
            for (int j2 = 0; j2 < 4; j2++) {
                float2 pv = upk2(acc1[i][j2]);
                int c0 = tx * 8 + j2 * 2;
                hs[c0 * 68 + ty * 4 + i] = fmaxf(pv.x + b1v[c0], 0.f);
                hs[(c0 + 1) * 68 + ty * 4 + i] = fmaxf(pv.y + b1v[c0 + 1], 0.f);
            }
    }
    __syncthreads();
    // ---- FFN GEMM2 (128->64) ----
#pragma unroll
    for (int i = 0; i < 32; i++) {
        int idx = tid + i * 256;
        sw[(idx >> 6) * 68 + (idx & 63)] = W2[idx];
    }
    __syncthreads();
    ull acc2[2][4] = {};
#pragma unroll
    for (int k = 0; k < 128; k++) {
        ull a0 = *(const ull*)&hs[k * 68 + ty * 4];
        ull a1 = *(const ull*)&hs[k * 68 + ty * 4 + 2];
        float4 bv = *(const float4*)&sw[k * 68 + tx * 4];
        ull b2[4] = {pk2(bv.x, bv.x), pk2(bv.y, bv.y), pk2(bv.z, bv.z), pk2(bv.w, bv.w)};
#pragma unroll
        for (int j = 0; j < 4; j++) { fma2(acc2[0][j], a0, b2[j]); fma2(acc2[1][j], a1, b2[j]); }
    }
    __syncthreads();   // W2 reads done; reuse sw for C
#pragma unroll
    for (int i2 = 0; i2 < 2; i2++) {
        float2 p0 = upk2(acc2[i2][0]), p1 = upk2(acc2[i2][1]);
        float2 p2 = upk2(acc2[i2][2]), p3 = upk2(acc2[i2][3]);
        int r0 = ty * 4 + i2 * 2;
        sw[r0 * 68 + tx * 4] = p0.x + b2v[tx * 4];
        sw[r0 * 68 + tx * 4 + 1] = p1.x + b2v[tx * 4 + 1];
        sw[r0 * 68 + tx * 4 + 2] = p2.x + b2v[tx * 4 + 2];
        sw[r0 * 68 + tx * 4 + 3] = p3.x + b2v[tx * 4 + 3];
        sw[(r0 + 1) * 68 + tx * 4] = p0.y + b2v[tx * 4];
        sw[(r0 + 1) * 68 + tx * 4 + 1] = p1.y + b2v[tx * 4 + 1];
        sw[(r0 + 1) * 68 + tx * 4 + 2] = p2.y + b2v[tx * 4 + 2];
        sw[(r0 + 1) * 68 + tx * 4 + 3] = p3.y + b2v[tx * 4 + 3];
    }
    __syncthreads();
    // ---- LN2 (residual from xs = LN1 out) -> g_x, regs ----
    int r2 = tid >> 2, p2 = tid & 3;
    float outs[16];
    {
        float vals[16];
        float sum = 0.f;
#pragma unroll
        for (int j = 0; j < 16; j++) {
            int c = p2 * 16 + j;
            float t = sw[r2 * 68 + c] + xs[c * 68 + r2];
            vals[j] = t; sum += t;
        }
        sum += __shfl_xor_sync(0xffffffffu, sum, 1);
        sum += __shfl_xor_sync(0xffffffffu, sum, 2);
        float mean = sum * (1.f / 64.f);
        float vsum = 0.f;
#pragma unroll
        for (int j = 0; j < 16; j++) { float d = vals[j] - mean; vsum += d * d; }
        vsum += __shfl_xor_sync(0xffffffffu, vsum, 1);
        vsum += __shfl_xor_sync(0xffffffffu, vsum, 2);
        float rstd = rsqrtf(vsum * (1.f / 64.f) + 1e-5f);
#pragma unroll
        for (int j = 0; j < 16; j++) {
            int c = p2 * 16 + j;
            outs[j] = (vals[j] - mean) * rstd * g2v[c] + be2[c];
            g_x[(n0 + r2) * HD + c] = outs[j];
        }
    }
    // ---- QKV for next layer ----
    if (Wq) {
        __syncthreads();   // residual reads of xs done
#pragma unroll
        for (int j = 0; j < 16; j++) xs[(p2 * 16 + j) * 68 + r2] = outs[j];
        qkv_tail(xs, sw, tid, n0, Wq, Wk, Wv, qo, ko, vo);
    }
}

// ================= readout =================
__global__ void readout_kernel(const int* __restrict__ agent, const float* __restrict__ Wr,
                               const float* __restrict__ br) {
    int t = blockIdx.x * blockDim.x + threadIdx.x;
    if (t >= NB * AD) return;
    int b = t / AD, a = t % AD;
    int node = agent[b];
    float s = br[a];
    const float* xr = g_x + node * HD;
#pragma unroll
    for (int h = 0; h < HD; h++) s += xr[h] * Wr[h * AD + a];
    g_gat[t] = s;
}

// ================= small GEMM helpers (M=128) =================
__global__ void init_bias_kernel(float* dst, const float* __restrict__ bias, int rows, int cols) {
    int idx = blockIdx.x * blockDim.x + threadIdx.x;
    if (idx < rows * cols) dst[idx] = bias[idx % cols];
}
__global__ void tanh_kernel(float* dst, const float* __restrict__ src, int n) {
    int idx = blockIdx.x * blockDim.x + threadIdx.x;
    if (idx < n) dst[idx] = tanhf(src[idx]);
}
__global__ void gemm_partial_kernel(const float* __restrict__ Apre, int preLen, int preLd,
                                    const float* __restrict__ Amain, int mainLd,
                                    const float* __restrict__ W, int ldw, int Ktot,
                                    float* Cacc, int ldc) {
    __shared__ float As[32 * 132];
    __shared__ float Ws[32 * 68];
    int colBase = blockIdx.x * 64;
    int kchunks = (Ktot + 31) / 32;
    int per = (kchunks + gridDim.y - 1) / gridDim.y;
    int c0 = blockIdx.y * per;
    int c1 = min(c0 + per, kchunks);
    int tid = threadIdx.x;
    int ty = tid >> 4, tx = tid & 15;
    ull acc[4][4] = {};
    for (int c = c0; c < c1; c++) {
        int kb = c * 32;
        __syncthreads();
#pragma unroll
        for (int i = 0; i < 16; i++) {
            int idx = tid + i * 256;
            int r = idx >> 5, kk = idx & 31;
            int k = kb + kk;
            float vv = 0.f;
            if (k < Ktot)
                vv = (k < preLen) ? Apre[r * preLd + k] : Amain[r * mainLd + k - preLen];
            As[kk * 132 + r] = vv;
        }
#pragma unroll
        for (int i = 0; i < 8; i++) {
            int idx = tid + i * 256;
            int kk = idx >> 6, j = idx & 63;
            int k = kb + kk;
            Ws[kk * 68 + j] = (k < Ktot) ? W[k * ldw + colBase + j] : 0.f;
        }
        __syncthreads();
#pragma unroll
        for (int kk = 0; kk < 32; kk++) {
            ull a2[4];
#pragma unroll
            for (int i2 = 0; i2 < 4; i2++)
                a2[i2] = *(const ull*)&As[kk * 132 + ty * 8 + i2 * 2];
            float4 bv = *(const float4*)&Ws[kk * 68 + tx * 4];
            ull b2[4] = {pk2(bv.x, bv.x), pk2(bv.y, bv.y), pk2(bv.z, bv.z), pk2(bv.w, bv.w)};
#pragma unroll
            for (int i2 = 0; i2 < 4; i2++)
#pragma unroll
                for (int j = 0; j < 4; j++) fma2(acc[i2][j], a2[i2], b2[j]);
        }
    }
#pragma unroll
    for (int i2 = 0; i2 < 4; i2++)
#pragma unroll
        for (int j = 0; j < 4; j++) {
            float2 pv = upk2(acc[i2][j]);
            atomicAdd(&Cacc[(ty * 8 + i2 * 2) * ldc + colBase + tx * 4 + j], pv.x);
            atomicAdd(&Cacc[(ty * 8 + i2 * 2 + 1) * ldc + colBase + tx * 4 + j], pv.y);
        }
}

// ================= heads =================
__global__ void logits_kernel(const float* __restrict__ Wlog, const float* __restrict__ blog,
                              float* out) {
    int t = blockIdx.x * blockDim.x + threadIdx.x;
    if (t >= NB * NOUTD) return;
    int b = t / NOUTD, o = t % NOUTD;
    float s = blog[o];
    const float* fr = g_feat2 + b * HSD;
    for (int k = 0; k < HSD; k++) s += fr[k] * Wlog[k * NOUTD + o];
    out[t] = s;
}
__global__ void value_kernel(const float* __restrict__ Wvo, const float* __restrict__ bvo,
                             float* out) {
    int b = blockIdx.x * blockDim.x + threadIdx.x;
    if (b >= NB) return;
    float s = bvo[0];
    const float* vr = g_vh2 + b * VHD;
#pragma unroll
    for (int k = 0; k < VHD; k++) s += vr[k] * Wvo[k];
    out[NB * NOUTD + b] = s;
}

// ================= launch =================
extern "C" void kernel_launch(void* const* d_in, const int* in_sizes, int n_in,
                              void* d_out, int out_size) {
    const float* nf     = (const float*)d_in[0];
    const float* obs    = (const float*)d_in[1];
    const int*   esrc   = (const int*)d_in[2];
    const int*   edst   = (const int*)d_in[3];
    const int*   agent  = (const int*)d_in[4];
    const float* Win    = (const float*)d_in[5];
    const float* Wq     = (const float*)d_in[6];
    const float* Wk     = (const float*)d_in[7];
    const float* Wv     = (const float*)d_in[8];
    const float* Wo     = (const float*)d_in[9];
    const float* ln1g   = (const float*)d_in[10];
    const float* ln1b   = (const float*)d_in[11];
    const float* W1     = (const float*)d_in[12];
    const float* b1     = (const float*)d_in[13];
    const float* W2     = (const float*)d_in[14];
    const float* b2     = (const float*)d_in[15];
    const float* ln2g   = (const float*)d_in[16];
    const float* ln2b   = (const float*)d_in[17];
    const float* Wr     = (const float*)d_in[18];
    const float* br     = (const float*)d_in[19];
    const float* Wp1    = (const float*)d_in[20];
    const float* bp1    = (const float*)d_in[21];
    const float* Wp2    = (const float*)d_in[22];
    const float* bp2    = (const float*)d_in[23];
    const float* Wlog   = (const float*)d_in[24];
    const float* blog   = (const float*)d_in[25];
    const float* Wv1    = (const float*)d_in[26];
    const float* bv1    = (const float*)d_in[27];
    const float* Wv2    = (const float*)d_in[28];
    const float* bv2    = (const float*)d_in[29];
    const float* Wvo    = (const float*)d_in[30];
    const float* bvo    = (const float*)d_in[31];
    float* out = (float*)d_out;

    cudaFuncSetAttribute(post_kernel, cudaFuncAttributeMaxDynamicSharedMemorySize, POST_SMEM);

    float *p_gat, *p_feat, *p_feat2, *p_vh, *p_vh2, *p_pacc;
    float *qA, *kA, *vA, *qB, *kB, *vB;
    int* p_deg;
    cudaGetSymbolAddress((void**)&p_gat, g_gat);
    cudaGetSymbolAddress((void**)&p_feat, g_feat);
    cudaGetSymbolAddress((void**)&p_feat2, g_feat2);
    cudaGetSymbolAddress((void**)&p_vh, g_vh);
    cudaGetSymbolAddress((void**)&p_vh2, g_vh2);
    cudaGetSymbolAddress((void**)&p_pacc, g_pacc);
    cudaGetSymbolAddress((void**)&qA, g_qA);
    cudaGetSymbolAddress((void**)&kA, g_kA);
    cudaGetSymbolAddress((void**)&vA, g_vA);
    cudaGetSymbolAddress((void**)&qB, g_qB);
    cudaGetSymbolAddress((void**)&kB, g_kB);
    cudaGetSymbolAddress((void**)&vB, g_vB);
    cudaGetSymbolAddress((void**)&p_deg, g_deg);

    // CSR build
    cudaMemsetAsync(p_deg, 0, TOTN * sizeof(int));
    hist_kernel<<<(NE + 255) / 256, 256>>>(edst);
    scan1_kernel<<<SCAN_BLKS, 256>>>();
    scan2_kernel<<<1, 128>>>();
    scan3_kernel<<<(TOTN + 255) / 256, 256>>>();
    scatter_kernel<<<(NE + 255) / 256, 256>>>(esrc, edst);

    // inproj + QKV layer0
    pre_kernel<<<TOTN / 64, 256>>>(nf, Win, Wq, Wk, Wv, qA, kA, vA);

    for (int l = 0; l < NL; l++) {
        const float* qi = (l & 1) ? qB : qA;
        const float* ki = (l & 1) ? kB : kA;
        const float* vi = (l & 1) ? vB : vA;
        float* qo = (l & 1) ? qA : qB;
        float* ko = (l & 1) ? kA : kB;
        float* vo = (l & 1) ? vA : vB;
        bool last = (l == NL - 1);
        post_kernel<<<TOTN / 64, 256, POST_SMEM>>>(
            qi, ki, vi,
            Wo + l * HD * HD, ln1g + l * HD, ln1b + l * HD,
            W1 + l * HD * 2 * HD, b1 + l * 2 * HD,
            W2 + l * 2 * HD * HD, b2 + l * HD,
            ln2g + l * HD, ln2b + l * HD,
            last ? nullptr : Wq + (l + 1) * HD * HD,
            last ? nullptr : Wk + (l + 1) * HD * HD,
            last ? nullptr : Wv + (l + 1) * HD * HD,
            qo, ko, vo);
    }

    readout_kernel<<<(NB * AD + 255) / 256, 256>>>(agent, Wr, br);

    // policy head
    init_bias_kernel<<<(NB * HSD + 255) / 256, 256>>>(p_pacc, bp1, NB, HSD);
    gemm_partial_kernel<<<dim3(8, 8), 256>>>(p_gat, AD, AD, obs, OBSD, Wp1, HSD, AD + OBSD,
                                             p_pacc, HSD);
    tanh_kernel<<<(NB * HSD + 255) / 256, 256>>>(p_feat, p_pacc, NB * HSD);

    init_bias_kernel<<<(NB * HSD + 255) / 256, 256>>>(p_pacc, bp2, NB, HSD);
    gemm_partial_kernel<<<dim3(8, 4), 256>>>(nullptr, 0, 0, p_feat, HSD, Wp2, HSD, HSD,
                                             p_pacc, HSD);
    tanh_kernel<<<(NB * HSD + 255) / 256, 256>>>(p_feat2, p_pacc, NB * HSD);

    logits_kernel<<<(NB * NOUTD + 255) / 256, 256>>>(Wlog, blog, out);

    // value head
    init_bias_kernel<<<(NB * VHD + 255) / 256, 256>>>(p_pacc, bv1, NB, VHD);
    gemm_partial_kernel<<<dim3(2, 8), 256>>>(nullptr, 0, 0, obs, OBSD, Wv1, VHD, OBSD,
                                             p_pacc, VHD);
    tanh_kernel<<<(NB * VHD + 255) / 256, 256>>>(p_vh, p_pacc, NB * VHD);

    init_bias_kernel<<<(NB * VHD + 255) / 256, 256>>>(p_pacc, bv2, NB, VHD);
    gemm_partial_kernel<<<dim3(2, 1), 256>>>(nullptr, 0, 0, p_vh, VHD, Wv2, VHD, VHD,
                                             p_pacc, VHD);
    tanh_kernel<<<(NB * VHD + 255) / 256, 256>>>(p_vh2, p_pacc, NB * VHD);

    value_kernel<<<1, NB>>>(Wvo, bvo, out);
}